// round 1
// baseline (speedup 1.0000x reference)
#include <cuda_runtime.h>
#include <cuda_bf16.h>

// Problem constants (B=8, N=256, H=128)
#define BB 8
#define NN 256
#define HH 128
#define ROWS (BB * NN)        // 2048
#define TI 16                 // i-rows per edge CTA
#define TJ 32                 // j-tile in smem
#define NSPLIT 2              // j-range split for more CTAs

// Scratch (allocation-free rule: __device__ globals)
__device__ float g_P[ROWS * HH];          // node @ We1[0:H] + be1
__device__ float g_Q[ROWS * HH];          // node @ We1[H:2H]
__device__ float g_S[NSPLIT][ROWS * HH];  // partial sums of masked silu(hidden)

__device__ __forceinline__ float fast_sigmoid(float x) {
    // 1 / (1 + 2^(-x*log2e)); ex2/rcp approx err ~2^-22 — far below tolerance
    float e;
    asm("ex2.approx.f32 %0, %1;" : "=f"(e) : "f"(-1.4426950408889634f * x));
    float r;
    asm("rcp.approx.f32 %0, %1;" : "=f"(r) : "f"(1.0f + e));
    return r;
}

// ---------------------------------------------------------------------------
// Kernel 1: P = node @ We1[0:H] + be1 ; Q = node @ We1[H:2H]
// 16 rows per CTA, 128 threads (thread = output column k)
// ---------------------------------------------------------------------------
__global__ void k_pq(const float* __restrict__ node,
                     const float* __restrict__ We1,
                     const float* __restrict__ be1) {
    __shared__ float xs[16][HH];
    int row0 = blockIdx.x * 16;
    int k = threadIdx.x;
#pragma unroll
    for (int r = 0; r < 16; r++) xs[r][k] = node[(row0 + r) * HH + k];
    __syncthreads();

    float accp[16], accq[16];
    float b1 = be1[k];
#pragma unroll
    for (int r = 0; r < 16; r++) { accp[r] = b1; accq[r] = 0.0f; }

    for (int h0 = 0; h0 < HH; h0 += 4) {
        float w1[4], w2[4];
#pragma unroll
        for (int e = 0; e < 4; e++) {
            w1[e] = We1[(h0 + e) * HH + k];
            w2[e] = We1[(HH + h0 + e) * HH + k];
        }
#pragma unroll
        for (int r = 0; r < 16; r++) {
            float4 x = *(const float4*)&xs[r][h0];
            accp[r] = fmaf(x.x, w1[0], accp[r]);
            accp[r] = fmaf(x.y, w1[1], accp[r]);
            accp[r] = fmaf(x.z, w1[2], accp[r]);
            accp[r] = fmaf(x.w, w1[3], accp[r]);
            accq[r] = fmaf(x.x, w2[0], accq[r]);
            accq[r] = fmaf(x.y, w2[1], accq[r]);
            accq[r] = fmaf(x.z, w2[2], accq[r]);
            accq[r] = fmaf(x.w, w2[3], accq[r]);
        }
    }
#pragma unroll
    for (int r = 0; r < 16; r++) {
        g_P[(row0 + r) * HH + k] = accp[r];
        g_Q[(row0 + r) * HH + k] = accq[r];
    }
}

// ---------------------------------------------------------------------------
// Kernel 2: S[b,i,k] = sum_j mask_j * silu(P[b,i,k] + Q[b,j,k] + dist_ij*wd[k])
// grid (NSPLIT, N/TI, B), 256 threads. Thread = (i_local, 8 k-values).
// ---------------------------------------------------------------------------
__global__ __launch_bounds__(256)
void k_edge(const float* __restrict__ pos,
            const float* __restrict__ mask,
            const float* __restrict__ We1) {
    __shared__ float qsm[TJ][HH];     // 16 KB
    __shared__ float bsm[TI][HH];     // 8 KB
    __shared__ float4 pjs[TJ];
    __shared__ float4 pis[TI];
    __shared__ float msm[TJ];

    int js = blockIdx.x;
    int i0 = blockIdx.y * TI;
    int b  = blockIdx.z;
    int tid = threadIdx.x;

    for (int idx = tid; idx < TI * HH; idx += 256) {
        bsm[idx >> 7][idx & 127] = g_P[(b * NN + i0 + (idx >> 7)) * HH + (idx & 127)];
    }
    if (tid < TI) {
        const float* p = &pos[(b * NN + i0 + tid) * 3];
        pis[tid] = make_float4(p[0], p[1], p[2], 0.0f);
    }
    __syncthreads();

    int il = tid >> 4;          // 0..15 local i
    int k0 = (tid & 15) * 8;    // 8 contiguous k per thread

    float wd[8], base[8], acc[8];
#pragma unroll
    for (int e = 0; e < 8; e++) {
        wd[e]   = We1[2 * HH * HH + k0 + e];  // row 256 of We1
        base[e] = bsm[il][k0 + e];
        acc[e]  = 0.0f;
    }
    float4 pi = pis[il];

    int j0 = js * (NN / NSPLIT);
    for (int jt = 0; jt < NN / NSPLIT; jt += TJ) {
        __syncthreads();
        const float4* qsrc = (const float4*)&g_Q[(b * NN + j0 + jt) * HH];
        for (int idx = tid; idx < TJ * HH / 4; idx += 256)
            ((float4*)qsm)[idx] = qsrc[idx];
        if (tid < TJ) {
            int jg = b * NN + j0 + jt + tid;
            const float* p = &pos[jg * 3];
            pjs[tid] = make_float4(p[0], p[1], p[2], 0.0f);
            msm[tid] = mask[jg];
        }
        __syncthreads();

#pragma unroll 4
        for (int jl = 0; jl < TJ; jl++) {
            float4 pj = pjs[jl];
            float dx = pi.x - pj.x, dy = pi.y - pj.y, dz = pi.z - pj.z;
            float sq = fmaf(dx, dx, fmaf(dy, dy, dz * dz));
            float dist = (sq > 0.0f) ? sqrtf(sq) : 0.0f;
            float mj = msm[jl];
            float4 qa = *(const float4*)&qsm[jl][k0];
            float4 qb = *(const float4*)&qsm[jl][k0 + 4];
            float qv[8] = {qa.x, qa.y, qa.z, qa.w, qb.x, qb.y, qb.z, qb.w};
#pragma unroll
            for (int e = 0; e < 8; e++) {
                float h = fmaf(dist, wd[e], base[e]) + qv[e];
                float s = fast_sigmoid(h);
                acc[e] = fmaf(h * mj, s, acc[e]);   // mj=0 -> contribution 0
            }
        }
    }
#pragma unroll
    for (int e = 0; e < 8; e++)
        g_S[js][(b * NN + i0 + il) * HH + k0 + e] = acc[e];
}

// ---------------------------------------------------------------------------
// Kernel 3: agg = mask_i*(S@We2 + cnt*be2)/max(mask_i*cnt,1);
//           u1 = silu(node@Wn1a + agg@Wn1b + bn1);
//           out = node + mask_i*(u1@Wn2 + bn2)
// 16 rows per CTA, 128 threads (thread = column k).
// ---------------------------------------------------------------------------
__global__ void k_final(const float* __restrict__ node,
                        const float* __restrict__ mask,
                        const float* __restrict__ We2,
                        const float* __restrict__ be2,
                        const float* __restrict__ Wn1,
                        const float* __restrict__ bn1,
                        const float* __restrict__ Wn2,
                        const float* __restrict__ bn2,
                        float* __restrict__ out) {
    __shared__ float Ssm[16][HH];
    __shared__ float Asm[16][HH];
    __shared__ float Xsm[16][HH];
    __shared__ float Usm[16][HH];
    __shared__ float msk[16];
    __shared__ float red[128];
    __shared__ float cntsh;

    int row0 = blockIdx.x * 16;
    int b = row0 >> 8;   // 256 rows per batch; 16-row blocks never straddle b
    int k = threadIdx.x;

#pragma unroll
    for (int r = 0; r < 16; r++) {
        Xsm[r][k] = node[(row0 + r) * HH + k];
        Ssm[r][k] = g_S[0][(row0 + r) * HH + k] + g_S[1][(row0 + r) * HH + k];
    }
    if (k < 16) msk[k] = mask[row0 + k];
    red[k] = mask[b * NN + k] + mask[b * NN + 128 + k];
    __syncthreads();
    if (k == 0) {
        float c = 0.0f;
        for (int i = 0; i < 128; i++) c += red[i];
        cntsh = c;
    }
    __syncthreads();
    float cnt = cntsh;

    // Stage A: agg
    {
        float acc[16];
#pragma unroll
        for (int r = 0; r < 16; r++) acc[r] = 0.0f;
        for (int h0 = 0; h0 < HH; h0 += 4) {
            float w[4];
#pragma unroll
            for (int e = 0; e < 4; e++) w[e] = We2[(h0 + e) * HH + k];
#pragma unroll
            for (int r = 0; r < 16; r++) {
                float4 s = *(const float4*)&Ssm[r][h0];
                acc[r] = fmaf(s.x, w[0], acc[r]);
                acc[r] = fmaf(s.y, w[1], acc[r]);
                acc[r] = fmaf(s.z, w[2], acc[r]);
                acc[r] = fmaf(s.w, w[3], acc[r]);
            }
        }
        float be2k = be2[k];
#pragma unroll
        for (int r = 0; r < 16; r++) {
            float denom = fmaxf(msk[r] * cnt, 1.0f);
            Asm[r][k] = msk[r] * (acc[r] + cnt * be2k) / denom;
        }
    }
    __syncthreads();

    // Stage B: u1 = silu([node, agg] @ Wn1 + bn1)
    {
        float acc[16];
        float b1 = bn1[k];
#pragma unroll
        for (int r = 0; r < 16; r++) acc[r] = b1;
        for (int h0 = 0; h0 < HH; h0 += 4) {
            float w1[4], w2[4];
#pragma unroll
            for (int e = 0; e < 4; e++) {
                w1[e] = Wn1[(h0 + e) * HH + k];
                w2[e] = Wn1[(HH + h0 + e) * HH + k];
            }
#pragma unroll
            for (int r = 0; r < 16; r++) {
                float4 x = *(const float4*)&Xsm[r][h0];
                float4 a = *(const float4*)&Asm[r][h0];
                acc[r] = fmaf(x.x, w1[0], acc[r]);
                acc[r] = fmaf(x.y, w1[1], acc[r]);
                acc[r] = fmaf(x.z, w1[2], acc[r]);
                acc[r] = fmaf(x.w, w1[3], acc[r]);
                acc[r] = fmaf(a.x, w2[0], acc[r]);
                acc[r] = fmaf(a.y, w2[1], acc[r]);
                acc[r] = fmaf(a.z, w2[2], acc[r]);
                acc[r] = fmaf(a.w, w2[3], acc[r]);
            }
        }
#pragma unroll
        for (int r = 0; r < 16; r++) {
            float h = acc[r];
            Usm[r][k] = h * fast_sigmoid(h);
        }
    }
    __syncthreads();

    // Stage C: out = node + mask_i * (u1 @ Wn2 + bn2)
    {
        float acc[16];
        float b2 = bn2[k];
#pragma unroll
        for (int r = 0; r < 16; r++) acc[r] = b2;
        for (int h0 = 0; h0 < HH; h0 += 4) {
            float w[4];
#pragma unroll
            for (int e = 0; e < 4; e++) w[e] = Wn2[(h0 + e) * HH + k];
#pragma unroll
            for (int r = 0; r < 16; r++) {
                float4 u = *(const float4*)&Usm[r][h0];
                acc[r] = fmaf(u.x, w[0], acc[r]);
                acc[r] = fmaf(u.y, w[1], acc[r]);
                acc[r] = fmaf(u.z, w[2], acc[r]);
                acc[r] = fmaf(u.w, w[3], acc[r]);
            }
        }
#pragma unroll
        for (int r = 0; r < 16; r++)
            out[(row0 + r) * HH + k] = Xsm[r][k] + msk[r] * acc[r];
    }
}

extern "C" void kernel_launch(void* const* d_in, const int* in_sizes, int n_in,
                              void* d_out, int out_size) {
    (void)in_sizes; (void)n_in; (void)out_size;
    const float* node = (const float*)d_in[0];
    const float* pos  = (const float*)d_in[1];
    const float* mask = (const float*)d_in[2];
    const float* We1  = (const float*)d_in[3];
    const float* be1  = (const float*)d_in[4];
    const float* We2  = (const float*)d_in[5];
    const float* be2  = (const float*)d_in[6];
    const float* Wn1  = (const float*)d_in[7];
    const float* bn1  = (const float*)d_in[8];
    const float* Wn2  = (const float*)d_in[9];
    const float* bn2  = (const float*)d_in[10];
    float* out = (float*)d_out;

    k_pq<<<ROWS / 16, 128>>>(node, We1, be1);
    k_edge<<<dim3(NSPLIT, NN / TI, BB), 256>>>(pos, mask, We1);
    k_final<<<ROWS / 16, 128>>>(node, mask, We2, be2, Wn1, bn1, Wn2, bn2, out);
}

// round 2
// speedup vs baseline: 1.4288x; 1.4288x over previous
#include <cuda_runtime.h>
#include <cuda_bf16.h>

// Problem constants (B=8, N=256, H=128)
#define BB 8
#define NN 256
#define HH 128
#define ROWS (BB * NN)        // 2048
#define TI 16                 // i-rows per edge CTA
#define TJ 32                 // j-tile in smem
#define NSPLIT 2              // j-range split

typedef unsigned long long ull;

// Scratch (allocation-free rule: __device__ globals)
// g_P holds 0.5*(node@We1a + be1); g_Q holds 0.5*(node@We1b)  (pre-halved for tanh-silu)
__device__ float g_P[ROWS * HH];
__device__ float g_Q[ROWS * HH];
__device__ float g_S[NSPLIT][ROWS * HH];  // partial sums of masked silu(hidden), exact scale

// ---------------- packed f32x2 + MUFU helpers ----------------
__device__ __forceinline__ ull fma2(ull a, ull b, ull c) {
    ull d; asm("fma.rn.f32x2 %0, %1, %2, %3;" : "=l"(d) : "l"(a), "l"(b), "l"(c)); return d;
}
__device__ __forceinline__ ull add2(ull a, ull b) {
    ull d; asm("add.rn.f32x2 %0, %1, %2;" : "=l"(d) : "l"(a), "l"(b)); return d;
}
__device__ __forceinline__ ull mul2(ull a, ull b) {
    ull d; asm("mul.rn.f32x2 %0, %1, %2;" : "=l"(d) : "l"(a), "l"(b)); return d;
}
__device__ __forceinline__ ull pack2(float lo, float hi) {
    ull d; asm("mov.b64 %0, {%1, %2};" : "=l"(d) : "f"(lo), "f"(hi)); return d;
}
__device__ __forceinline__ void unpack2(ull v, float& lo, float& hi) {
    asm("mov.b64 {%0, %1}, %2;" : "=f"(lo), "=f"(hi) : "l"(v));
}
__device__ __forceinline__ float tanhfast(float x) {
    float y; asm("tanh.approx.f32 %0, %1;" : "=f"(y) : "f"(x)); return y;
}
__device__ __forceinline__ float fast_sigmoid(float x) {
    float e; asm("ex2.approx.f32 %0, %1;" : "=f"(e) : "f"(-1.4426950408889634f * x));
    float r; asm("rcp.approx.f32 %0, %1;" : "=f"(r) : "f"(1.0f + e));
    return r;
}

// ---------------------------------------------------------------------------
// Kernel 1: P' = 0.5*(node @ We1[0:H] + be1) ; Q' = 0.5*(node @ We1[H:2H])
// 8 rows per CTA, 256 threads: tid<128 -> P column k, tid>=128 -> Q column k.
// ---------------------------------------------------------------------------
__global__ __launch_bounds__(256)
void k_pq(const float* __restrict__ node,
          const float* __restrict__ We1,
          const float* __restrict__ be1) {
    __shared__ float xs[8][HH];
    int row0 = blockIdx.x * 8;
    int tid = threadIdx.x;
    int k = tid & 127;
    int half = tid >> 7;

    for (int idx = tid; idx < 8 * HH; idx += 256)
        xs[idx >> 7][idx & 127] = node[(row0 + (idx >> 7)) * HH + (idx & 127)];
    __syncthreads();

    const float* W = We1 + half * HH * HH;
    float acc[8];
    float b = half ? 0.0f : be1[k];
#pragma unroll
    for (int r = 0; r < 8; r++) acc[r] = b;

#pragma unroll 4
    for (int h0 = 0; h0 < HH; h0 += 4) {
        float w[4];
#pragma unroll
        for (int e = 0; e < 4; e++) w[e] = W[(h0 + e) * HH + k];
#pragma unroll
        for (int r = 0; r < 8; r++) {
            float4 x = *(const float4*)&xs[r][h0];
            acc[r] = fmaf(x.x, w[0], acc[r]);
            acc[r] = fmaf(x.y, w[1], acc[r]);
            acc[r] = fmaf(x.z, w[2], acc[r]);
            acc[r] = fmaf(x.w, w[3], acc[r]);
        }
    }
    float* dst = half ? g_Q : g_P;
#pragma unroll
    for (int r = 0; r < 8; r++)
        dst[(row0 + r) * HH + k] = 0.5f * acc[r];
}

// ---------------------------------------------------------------------------
// Kernel 2: S[b,i,k] = sum_j mj * silu(h),  h/2 = P'_i + Q'_j + dist*wd'
// silu(h) = (h/2)*(1 + tanh(h/2)).  Packed f32x2 math, 1 MUFU.TANH per elem.
// grid (NSPLIT, N/TI, B), 256 threads. Thread = (i_local, 8 k-values).
// ---------------------------------------------------------------------------
__global__ __launch_bounds__(256)
void k_edge(const float* __restrict__ pos,
            const float* __restrict__ mask,
            const float* __restrict__ We1) {
    __shared__ float qsm[TJ][HH];     // 16 KB  (Q'/2-scale tile)
    __shared__ float bsm[TI][HH];     // 8 KB   (P' rows)
    __shared__ float4 pjs[TJ];
    __shared__ float4 pis[TI];
    __shared__ float msm[TJ];

    int js = blockIdx.x;
    int i0 = blockIdx.y * TI;
    int b  = blockIdx.z;
    int tid = threadIdx.x;

    for (int idx = tid; idx < TI * HH; idx += 256)
        bsm[idx >> 7][idx & 127] = g_P[(b * NN + i0 + (idx >> 7)) * HH + (idx & 127)];
    if (tid < TI) {
        const float* p = &pos[(b * NN + i0 + tid) * 3];
        pis[tid] = make_float4(p[0], p[1], p[2], 0.0f);
    }
    __syncthreads();

    int il = tid >> 4;
    int k0 = (tid & 15) * 8;

    ull base2[4], wd2[4], acc2[4];
#pragma unroll
    for (int p = 0; p < 4; p++) {
        float w0 = 0.5f * We1[2 * HH * HH + k0 + 2 * p];
        float w1 = 0.5f * We1[2 * HH * HH + k0 + 2 * p + 1];
        wd2[p] = pack2(w0, w1);
        base2[p] = ((const ull*)&bsm[il][k0])[p];
        acc2[p] = 0ULL;
    }
    float4 pi = pis[il];

    int j0 = js * (NN / NSPLIT);
    for (int jt = 0; jt < NN / NSPLIT; jt += TJ) {
        __syncthreads();
        const float4* qsrc = (const float4*)&g_Q[(b * NN + j0 + jt) * HH];
        for (int idx = tid; idx < TJ * HH / 4; idx += 256)
            ((float4*)qsm)[idx] = qsrc[idx];
        if (tid < TJ) {
            int jg = b * NN + j0 + jt + tid;
            const float* p = &pos[jg * 3];
            pjs[tid] = make_float4(p[0], p[1], p[2], 0.0f);
            msm[tid] = mask[jg];
        }
        __syncthreads();

#pragma unroll 4
        for (int jl = 0; jl < TJ; jl++) {
            float4 pj = pjs[jl];
            float dx = pi.x - pj.x, dy = pi.y - pj.y, dz = pi.z - pj.z;
            float sq = fmaf(dx, dx, fmaf(dy, dy, dz * dz));
            float rs; asm("rsqrt.approx.f32 %0, %1;" : "=f"(rs) : "f"(sq));
            float dist = (sq > 0.0f) ? sq * rs : 0.0f;
            float mj = msm[jl];
            ull dist2 = pack2(dist, dist);
            ull mj2 = pack2(mj, mj);
            ulonglong2 qa = *(const ulonglong2*)&qsm[jl][k0];
            ulonglong2 qb = *(const ulonglong2*)&qsm[jl][k0 + 4];
            ull qv[4] = {qa.x, qa.y, qb.x, qb.y};
#pragma unroll
            for (int p = 0; p < 4; p++) {
                ull h2 = fma2(dist2, wd2[p], add2(base2[p], qv[p]));  // = h/2
                float hl, hh; unpack2(h2, hl, hh);
                ull t2 = pack2(tanhfast(hl), tanhfast(hh));
                ull g2 = mul2(h2, mj2);
                acc2[p] = add2(acc2[p], g2);
                acc2[p] = fma2(g2, t2, acc2[p]);                      // += g*(1+t)
            }
        }
    }
    float* dst = &g_S[js][(b * NN + i0 + il) * HH + k0];
#pragma unroll
    for (int p = 0; p < 4; p++) {
        float lo, hi; unpack2(acc2[p], lo, hi);
        dst[2 * p] = lo;
        dst[2 * p + 1] = hi;
    }
}

// ---------------------------------------------------------------------------
// Kernel 3: agg = mask_i*(S@We2 + cnt*be2)/max(mask_i*cnt,1);
//           u1 = silu([node, agg] @ Wn1 + bn1);
//           out = node + mask_i*(u1@Wn2 + bn2)
// 8 rows per CTA, 128 threads (thread = column k), 256 CTAs.
// ---------------------------------------------------------------------------
__global__ __launch_bounds__(128)
void k_final(const float* __restrict__ node,
             const float* __restrict__ mask,
             const float* __restrict__ We2,
             const float* __restrict__ be2,
             const float* __restrict__ Wn1,
             const float* __restrict__ bn1,
             const float* __restrict__ Wn2,
             const float* __restrict__ bn2,
             float* __restrict__ out) {
    __shared__ float Ssm[8][HH];
    __shared__ float Asm[8][HH];
    __shared__ float Xsm[8][HH];
    __shared__ float Usm[8][HH];
    __shared__ float msk[8];
    __shared__ float cntsh;

    int row0 = blockIdx.x * 8;
    int b = row0 >> 8;
    int k = threadIdx.x;

#pragma unroll
    for (int r = 0; r < 8; r++) {
        Xsm[r][k] = node[(row0 + r) * HH + k];
        Ssm[r][k] = g_S[0][(row0 + r) * HH + k] + g_S[1][(row0 + r) * HH + k];
    }
    if (k < 8) msk[k] = mask[row0 + k];
    if (k < 32) {
        float c = 0.0f;
#pragma unroll
        for (int m = 0; m < 8; m++) c += mask[b * NN + k * 8 + m];
#pragma unroll
        for (int o = 16; o; o >>= 1) c += __shfl_xor_sync(0xffffffffu, c, o);
        if (k == 0) cntsh = c;
    }
    __syncthreads();
    float cnt = cntsh;

    // Stage A: agg
    {
        float acc[8];
#pragma unroll
        for (int r = 0; r < 8; r++) acc[r] = 0.0f;
#pragma unroll 4
        for (int h0 = 0; h0 < HH; h0 += 4) {
            float w[4];
#pragma unroll
            for (int e = 0; e < 4; e++) w[e] = We2[(h0 + e) * HH + k];
#pragma unroll
            for (int r = 0; r < 8; r++) {
                float4 s = *(const float4*)&Ssm[r][h0];
                acc[r] = fmaf(s.x, w[0], acc[r]);
                acc[r] = fmaf(s.y, w[1], acc[r]);
                acc[r] = fmaf(s.z, w[2], acc[r]);
                acc[r] = fmaf(s.w, w[3], acc[r]);
            }
        }
        float be2k = be2[k];
#pragma unroll
        for (int r = 0; r < 8; r++) {
            float denom = fmaxf(msk[r] * cnt, 1.0f);
            Asm[r][k] = msk[r] * (acc[r] + cnt * be2k) / denom;
        }
    }
    __syncthreads();

    // Stage B: u1 = silu([node, agg] @ Wn1 + bn1)
    {
        float acc[8];
        float b1 = bn1[k];
#pragma unroll
        for (int r = 0; r < 8; r++) acc[r] = b1;
#pragma unroll 4
        for (int h0 = 0; h0 < HH; h0 += 4) {
            float w1[4], w2[4];
#pragma unroll
            for (int e = 0; e < 4; e++) {
                w1[e] = Wn1[(h0 + e) * HH + k];
                w2[e] = Wn1[(HH + h0 + e) * HH + k];
            }
#pragma unroll
            for (int r = 0; r < 8; r++) {
                float4 x = *(const float4*)&Xsm[r][h0];
                float4 a = *(const float4*)&Asm[r][h0];
                acc[r] = fmaf(x.x, w1[0], acc[r]);
                acc[r] = fmaf(x.y, w1[1], acc[r]);
                acc[r] = fmaf(x.z, w1[2], acc[r]);
                acc[r] = fmaf(x.w, w1[3], acc[r]);
                acc[r] = fmaf(a.x, w2[0], acc[r]);
                acc[r] = fmaf(a.y, w2[1], acc[r]);
                acc[r] = fmaf(a.z, w2[2], acc[r]);
                acc[r] = fmaf(a.w, w2[3], acc[r]);
            }
        }
#pragma unroll
        for (int r = 0; r < 8; r++) {
            float h = acc[r];
            Usm[r][k] = h * fast_sigmoid(h);
        }
    }
    __syncthreads();

    // Stage C: out = node + mask_i * (u1 @ Wn2 + bn2)
    {
        float acc[8];
        float b2 = bn2[k];
#pragma unroll
        for (int r = 0; r < 8; r++) acc[r] = b2;
#pragma unroll 4
        for (int h0 = 0; h0 < HH; h0 += 4) {
            float w[4];
#pragma unroll
            for (int e = 0; e < 4; e++) w[e] = Wn2[(h0 + e) * HH + k];
#pragma unroll
            for (int r = 0; r < 8; r++) {
                float4 u = *(const float4*)&Usm[r][h0];
                acc[r] = fmaf(u.x, w[0], acc[r]);
                acc[r] = fmaf(u.y, w[1], acc[r]);
                acc[r] = fmaf(u.z, w[2], acc[r]);
                acc[r] = fmaf(u.w, w[3], acc[r]);
            }
        }
#pragma unroll
        for (int r = 0; r < 8; r++)
            out[(row0 + r) * HH + k] = Xsm[r][k] + msk[r] * acc[r];
    }
}

extern "C" void kernel_launch(void* const* d_in, const int* in_sizes, int n_in,
                              void* d_out, int out_size) {
    (void)in_sizes; (void)n_in; (void)out_size;
    const float* node = (const float*)d_in[0];
    const float* pos  = (const float*)d_in[1];
    const float* mask = (const float*)d_in[2];
    const float* We1  = (const float*)d_in[3];
    const float* be1  = (const float*)d_in[4];
    const float* We2  = (const float*)d_in[5];
    const float* be2  = (const float*)d_in[6];
    const float* Wn1  = (const float*)d_in[7];
    const float* bn1  = (const float*)d_in[8];
    const float* Wn2  = (const float*)d_in[9];
    const float* bn2  = (const float*)d_in[10];
    float* out = (float*)d_out;

    k_pq<<<ROWS / 8, 256>>>(node, We1, be1);
    k_edge<<<dim3(NSPLIT, NN / TI, BB), 256>>>(pos, mask, We1);
    k_final<<<ROWS / 8, 128>>>(node, mask, We2, be2, Wn1, bn1, Wn2, bn2, out);
}

// round 3
// speedup vs baseline: 1.6731x; 1.1709x over previous
#include <cuda_runtime.h>
#include <cuda_bf16.h>

// Problem constants (B=8, N=256, H=128)
#define BB 8
#define NN 256
#define HH 128
#define ROWS (BB * NN)        // 2048
#define TI 16                 // i-rows per edge CTA
#define TJ 32                 // j-tile in smem
#define NSPLIT 4              // j-range split

typedef unsigned long long ull;

// Scratch (allocation-free rule: __device__ globals)
// g_P holds 0.5*(node@We1a + be1); g_Q holds 0.5*(node@We1b)  (pre-halved for tanh-silu)
__device__ float g_P[ROWS * HH];
__device__ float g_Q[ROWS * HH];
__device__ float g_S[NSPLIT][ROWS * HH];  // partial sums of masked silu(hidden)

// ---------------- packed f32x2 + MUFU helpers ----------------
__device__ __forceinline__ ull fma2(ull a, ull b, ull c) {
    ull d; asm("fma.rn.f32x2 %0, %1, %2, %3;" : "=l"(d) : "l"(a), "l"(b), "l"(c)); return d;
}
__device__ __forceinline__ ull add2(ull a, ull b) {
    ull d; asm("add.rn.f32x2 %0, %1, %2;" : "=l"(d) : "l"(a), "l"(b)); return d;
}
__device__ __forceinline__ ull pack2(float lo, float hi) {
    ull d; asm("mov.b64 %0, {%1, %2};" : "=l"(d) : "f"(lo), "f"(hi)); return d;
}
__device__ __forceinline__ void unpack2(ull v, float& lo, float& hi) {
    asm("mov.b64 {%0, %1}, %2;" : "=f"(lo), "=f"(hi) : "l"(v));
}
__device__ __forceinline__ float tanhfast(float x) {
    float y; asm("tanh.approx.f32 %0, %1;" : "=f"(y) : "f"(x)); return y;
}
__device__ __forceinline__ float sqrtfast(float x) {
    float y; asm("sqrt.approx.f32 %0, %1;" : "=f"(y) : "f"(x)); return y;
}
__device__ __forceinline__ float fast_sigmoid(float x) {
    float e; asm("ex2.approx.f32 %0, %1;" : "=f"(e) : "f"(-1.4426950408889634f * x));
    float r; asm("rcp.approx.f32 %0, %1;" : "=f"(r) : "f"(1.0f + e));
    return r;
}

// ---------------------------------------------------------------------------
// Kernel 1: P' = 0.5*(node @ We1[0:H] + be1) ; Q' = 0.5*(node @ We1[H:2H])
// 8 rows/CTA, 256 threads (tid<128 -> P col k; tid>=128 -> Q col k).
// Weights double-buffered in registers, chunks of 16 -> latency hidden.
// ---------------------------------------------------------------------------
__global__ __launch_bounds__(256)
void k_pq(const float* __restrict__ node,
          const float* __restrict__ We1,
          const float* __restrict__ be1) {
    __shared__ __align__(16) float xs[8][HH];
    int row0 = blockIdx.x * 8;
    int tid = threadIdx.x;
    int k = tid & 127;
    int half = tid >> 7;

#pragma unroll
    for (int q = 0; q < 4; q++) {
        int idx = tid + q * 256;
        xs[idx >> 7][idx & 127] = node[(row0 + (idx >> 7)) * HH + (idx & 127)];
    }
    __syncthreads();

    const float* W = We1 + half * HH * HH + k;
    float acc[8];
    float b = half ? 0.0f : be1[k];
#pragma unroll
    for (int r = 0; r < 8; r++) acc[r] = b;

    float w0[16], w1[16];
#pragma unroll
    for (int e = 0; e < 16; e++) w0[e] = W[e * HH];

#pragma unroll
    for (int c = 0; c < 8; c++) {
        float* wc = (c & 1) ? w1 : w0;
        float* wn = (c & 1) ? w0 : w1;
        if (c < 7) {
#pragma unroll
            for (int e = 0; e < 16; e++) wn[e] = W[((c + 1) * 16 + e) * HH];
        }
#pragma unroll
        for (int g = 0; g < 4; g++) {
#pragma unroll
            for (int r = 0; r < 8; r++) {
                float4 x = *(const float4*)&xs[r][c * 16 + g * 4];
                acc[r] = fmaf(x.x, wc[g * 4 + 0], acc[r]);
                acc[r] = fmaf(x.y, wc[g * 4 + 1], acc[r]);
                acc[r] = fmaf(x.z, wc[g * 4 + 2], acc[r]);
                acc[r] = fmaf(x.w, wc[g * 4 + 3], acc[r]);
            }
        }
    }
    float* dst = half ? g_Q : g_P;
#pragma unroll
    for (int r = 0; r < 8; r++)
        dst[(row0 + r) * HH + k] = 0.5f * acc[r];
}

// ---------------------------------------------------------------------------
// Kernel 2: S[b,i,k] += mj * silu(h),  h/2 = P'_i + Q'_j + dist*wd'
// silu(h) = (h/2)*(1 + tanh(h/2)).  4 fma2 + 2 tanh per 2 elems.
// grid (NSPLIT, N/TI, B) = 512 CTAs, 256 threads.
// ---------------------------------------------------------------------------
__global__ __launch_bounds__(256)
void k_edge(const float* __restrict__ pos,
            const float* __restrict__ mask,
            const float* __restrict__ We1) {
    __shared__ __align__(16) float qsm[TJ][HH];
    __shared__ __align__(16) float bsm[TI][HH];
    __shared__ float4 pjs[TJ];
    __shared__ float4 pis[TI];
    __shared__ float msm[TJ];

    int js = blockIdx.x;
    int i0 = blockIdx.y * TI;
    int b  = blockIdx.z;
    int tid = threadIdx.x;

    for (int idx = tid; idx < TI * HH; idx += 256)
        bsm[idx >> 7][idx & 127] = g_P[(b * NN + i0 + (idx >> 7)) * HH + (idx & 127)];
    if (tid < TI) {
        const float* p = &pos[(b * NN + i0 + tid) * 3];
        pis[tid] = make_float4(p[0], p[1], p[2], 0.0f);
    }
    __syncthreads();

    int il = tid >> 4;
    int k0 = (tid & 15) * 8;

    ull base2[4], wd2[4], acc2[4];
#pragma unroll
    for (int p = 0; p < 4; p++) {
        float wlo = 0.5f * We1[2 * HH * HH + k0 + 2 * p];
        float whi = 0.5f * We1[2 * HH * HH + k0 + 2 * p + 1];
        wd2[p] = pack2(wlo, whi);
        base2[p] = ((const ull*)&bsm[il][k0])[p];
        acc2[p] = 0ULL;
    }
    float4 pi = pis[il];

    int j0 = js * (NN / NSPLIT);
#pragma unroll
    for (int jt = 0; jt < NN / NSPLIT; jt += TJ) {
        __syncthreads();
        const float4* qsrc = (const float4*)&g_Q[(b * NN + j0 + jt) * HH];
        for (int idx = tid; idx < TJ * HH / 4; idx += 256)
            ((float4*)qsm)[idx] = qsrc[idx];
        if (tid < TJ) {
            int jg = b * NN + j0 + jt + tid;
            const float* p = &pos[jg * 3];
            pjs[tid] = make_float4(p[0], p[1], p[2], 0.0f);
            msm[tid] = mask[jg];
        }
        __syncthreads();

#pragma unroll 4
        for (int jl = 0; jl < TJ; jl++) {
            float4 pj = pjs[jl];
            float dx = pi.x - pj.x, dy = pi.y - pj.y, dz = pi.z - pj.z;
            float sq = fmaf(dx, dx, fmaf(dy, dy, dz * dz));
            float dist = (sq > 0.0f) ? sqrtfast(sq) : 0.0f;
            float mj = msm[jl];
            ull dist2 = pack2(dist, dist);
            ull mj2 = pack2(mj, mj);
            ulonglong2 qa = *(const ulonglong2*)&qsm[jl][k0];
            ulonglong2 qb = *(const ulonglong2*)&qsm[jl][k0 + 4];
            ull qv[4] = {qa.x, qa.y, qb.x, qb.y};
#pragma unroll
            for (int p = 0; p < 4; p++) {
                ull h2 = fma2(dist2, wd2[p], add2(base2[p], qv[p]));  // h/2
                float hl, hh; unpack2(h2, hl, hh);
                ull t2 = pack2(tanhfast(hl), tanhfast(hh));
                ull s2 = fma2(h2, t2, h2);        // silu(h) = h2*(1+t)
                acc2[p] = fma2(mj2, s2, acc2[p]); // += mj * silu
            }
        }
    }
    float* dst = &g_S[js][(b * NN + i0 + il) * HH + k0];
#pragma unroll
    for (int p = 0; p < 4; p++) {
        float lo, hi; unpack2(acc2[p], lo, hi);
        dst[2 * p] = lo;
        dst[2 * p + 1] = hi;
    }
}

// ---------------------------------------------------------------------------
// Kernel 3: agg -> node MLP -> residual.  8 rows/CTA, 256 threads
// (thread = col k, row-half rb). Weight chunks double-buffered everywhere.
// ---------------------------------------------------------------------------
__global__ __launch_bounds__(256)
void k_final(const float* __restrict__ node,
             const float* __restrict__ mask,
             const float* __restrict__ We2,
             const float* __restrict__ be2,
             const float* __restrict__ Wn1,
             const float* __restrict__ bn1,
             const float* __restrict__ Wn2,
             const float* __restrict__ bn2,
             float* __restrict__ out) {
    __shared__ __align__(16) float Ssm[8][HH];
    __shared__ __align__(16) float XA[8][2 * HH];   // [X | A]
    __shared__ __align__(16) float Usm[8][HH];
    __shared__ float msk[8];
    __shared__ float cntsh;

    int row0 = blockIdx.x * 8;
    int b = row0 >> 8;
    int tid = threadIdx.x;
    int k = tid & 127;
    int rb = (tid >> 7) * 4;

#pragma unroll
    for (int q = 0; q < 4; q++) {
        int r = rb + q;
        int g = (row0 + r) * HH + k;
        XA[r][k] = node[g];
        Ssm[r][k] = g_S[0][g] + g_S[1][g] + g_S[2][g] + g_S[3][g];
    }
    if (tid < 8) msk[tid] = mask[row0 + tid];
    if (tid < 32) {
        float c = 0.0f;
#pragma unroll
        for (int m = 0; m < 8; m++) c += mask[b * NN + tid * 8 + m];
#pragma unroll
        for (int o = 16; o; o >>= 1) c += __shfl_xor_sync(0xffffffffu, c, o);
        if (tid == 0) cntsh = c;
    }
    __syncthreads();
    float cnt = cntsh;

    // Stage A: agg = msk*(S@We2 + cnt*be2)/max(msk*cnt,1)  -> XA[:, HH+k]
    {
        float acc[4] = {0.f, 0.f, 0.f, 0.f};
        const float* W = We2 + k;
        float w0[16], w1[16];
#pragma unroll
        for (int e = 0; e < 16; e++) w0[e] = W[e * HH];
#pragma unroll
        for (int c = 0; c < 8; c++) {
            float* wc = (c & 1) ? w1 : w0;
            float* wn = (c & 1) ? w0 : w1;
            if (c < 7) {
#pragma unroll
                for (int e = 0; e < 16; e++) wn[e] = W[((c + 1) * 16 + e) * HH];
            }
#pragma unroll
            for (int g = 0; g < 4; g++) {
#pragma unroll
                for (int q = 0; q < 4; q++) {
                    float4 s = *(const float4*)&Ssm[rb + q][c * 16 + g * 4];
                    acc[q] = fmaf(s.x, wc[g * 4 + 0], acc[q]);
                    acc[q] = fmaf(s.y, wc[g * 4 + 1], acc[q]);
                    acc[q] = fmaf(s.z, wc[g * 4 + 2], acc[q]);
                    acc[q] = fmaf(s.w, wc[g * 4 + 3], acc[q]);
                }
            }
        }
        float be2k = be2[k];
#pragma unroll
        for (int q = 0; q < 4; q++) {
            int r = rb + q;
            float denom = fmaxf(msk[r] * cnt, 1.0f);
            XA[r][HH + k] = msk[r] * (acc[q] + cnt * be2k) * (1.0f / denom);
        }
    }
    __syncthreads();

    // Stage B: u1 = silu(XA @ Wn1 + bn1)  (single 256-deep stream)
    {
        float b1 = bn1[k];
        float acc[4] = {b1, b1, b1, b1};
        const float* W = Wn1 + k;
        float w0[16], w1[16];
#pragma unroll
        for (int e = 0; e < 16; e++) w0[e] = W[e * HH];
#pragma unroll
        for (int c = 0; c < 16; c++) {
            float* wc = (c & 1) ? w1 : w0;
            float* wn = (c & 1) ? w0 : w1;
            if (c < 15) {
#pragma unroll
                for (int e = 0; e < 16; e++) wn[e] = W[((c + 1) * 16 + e) * HH];
            }
#pragma unroll
            for (int g = 0; g < 4; g++) {
#pragma unroll
                for (int q = 0; q < 4; q++) {
                    float4 x = *(const float4*)&XA[rb + q][c * 16 + g * 4];
                    acc[q] = fmaf(x.x, wc[g * 4 + 0], acc[q]);
                    acc[q] = fmaf(x.y, wc[g * 4 + 1], acc[q]);
                    acc[q] = fmaf(x.z, wc[g * 4 + 2], acc[q]);
                    acc[q] = fmaf(x.w, wc[g * 4 + 3], acc[q]);
                }
            }
        }
#pragma unroll
        for (int q = 0; q < 4; q++) {
            float h = acc[q];
            Usm[rb + q][k] = h * fast_sigmoid(h);
        }
    }
    __syncthreads();

    // Stage C: out = node + msk * (u1 @ Wn2 + bn2)
    {
        float b2 = bn2[k];
        float acc[4] = {b2, b2, b2, b2};
        const float* W = Wn2 + k;
        float w0[16], w1[16];
#pragma unroll
        for (int e = 0; e < 16; e++) w0[e] = W[e * HH];
#pragma unroll
        for (int c = 0; c < 8; c++) {
            float* wc = (c & 1) ? w1 : w0;
            float* wn = (c & 1) ? w0 : w1;
            if (c < 7) {
#pragma unroll
                for (int e = 0; e < 16; e++) wn[e] = W[((c + 1) * 16 + e) * HH];
            }
#pragma unroll
            for (int g = 0; g < 4; g++) {
#pragma unroll
                for (int q = 0; q < 4; q++) {
                    float4 u = *(const float4*)&Usm[rb + q][c * 16 + g * 4];
                    acc[q] = fmaf(u.x, wc[g * 4 + 0], acc[q]);
                    acc[q] = fmaf(u.y, wc[g * 4 + 1], acc[q]);
                    acc[q] = fmaf(u.z, wc[g * 4 + 2], acc[q]);
                    acc[q] = fmaf(u.w, wc[g * 4 + 3], acc[q]);
                }
            }
        }
#pragma unroll
        for (int q = 0; q < 4; q++) {
            int r = rb + q;
            out[(row0 + r) * HH + k] = XA[r][k] + msk[r] * acc[q];
        }
    }
}

extern "C" void kernel_launch(void* const* d_in, const int* in_sizes, int n_in,
                              void* d_out, int out_size) {
    (void)in_sizes; (void)n_in; (void)out_size;
    const float* node = (const float*)d_in[0];
    const float* pos  = (const float*)d_in[1];
    const float* mask = (const float*)d_in[2];
    const float* We1  = (const float*)d_in[3];
    const float* be1  = (const float*)d_in[4];
    const float* We2  = (const float*)d_in[5];
    const float* be2  = (const float*)d_in[6];
    const float* Wn1  = (const float*)d_in[7];
    const float* bn1  = (const float*)d_in[8];
    const float* Wn2  = (const float*)d_in[9];
    const float* bn2  = (const float*)d_in[10];
    float* out = (float*)d_out;

    k_pq<<<ROWS / 8, 256>>>(node, We1, be1);
    k_edge<<<dim3(NSPLIT, NN / TI, BB), 256>>>(pos, mask, We1);
    k_final<<<ROWS / 8, 256>>>(node, mask, We2, be2, Wn1, bn1, Wn2, bn2, out);
}

// round 4
// speedup vs baseline: 1.8544x; 1.1083x over previous
#include <cuda_runtime.h>
#include <cuda_bf16.h>

// Problem constants (B=8, N=256, H=128)
#define BB 8
#define NN 256
#define HH 128
#define ROWS (BB * NN)        // 2048
#define TI 16                 // i-rows per edge CTA
#define TJ 32                 // j-tile in smem
#define NSPLIT 8              // j-range split (inner range == TJ: single tile)

typedef unsigned long long ull;

// Scratch (allocation-free rule: __device__ globals)
// g_P holds 0.5*(node@We1a + be1); g_Q holds 0.5*(node@We1b)  (pre-halved for tanh-silu)
__device__ float g_P[ROWS * HH];
__device__ float g_Q[ROWS * HH];
__device__ float g_S[NSPLIT][ROWS * HH];  // partial sums of masked silu(hidden)

// ---------------- packed f32x2 + MUFU helpers ----------------
__device__ __forceinline__ ull fma2(ull a, ull b, ull c) {
    ull d; asm("fma.rn.f32x2 %0, %1, %2, %3;" : "=l"(d) : "l"(a), "l"(b), "l"(c)); return d;
}
__device__ __forceinline__ ull add2(ull a, ull b) {
    ull d; asm("add.rn.f32x2 %0, %1, %2;" : "=l"(d) : "l"(a), "l"(b)); return d;
}
__device__ __forceinline__ ull pack2(float lo, float hi) {
    ull d; asm("mov.b64 %0, {%1, %2};" : "=l"(d) : "f"(lo), "f"(hi)); return d;
}
__device__ __forceinline__ void unpack2(ull v, float& lo, float& hi) {
    asm("mov.b64 {%0, %1}, %2;" : "=f"(lo), "=f"(hi) : "l"(v));
}
__device__ __forceinline__ float tanhfast(float x) {
    float y; asm("tanh.approx.f32 %0, %1;" : "=f"(y) : "f"(x)); return y;
}
__device__ __forceinline__ float sqrtfast(float x) {
    float y; asm("sqrt.approx.f32 %0, %1;" : "=f"(y) : "f"(x)); return y;
}
__device__ __forceinline__ float fast_sigmoid(float x) {
    float e; asm("ex2.approx.f32 %0, %1;" : "=f"(e) : "f"(-1.4426950408889634f * x));
    float r; asm("rcp.approx.f32 %0, %1;" : "=f"(r) : "f"(1.0f + e));
    return r;
}

// ---------------------------------------------------------------------------
// Kernel 1: P' = 0.5*(node @ We1[0:H] + be1) ; Q' = 0.5*(node @ We1[H:2H])
// 8 rows/CTA, 256 threads (tid<128 -> P col k; tid>=128 -> Q col k).
// 32-wide weight chunks, double-buffered in registers (needs ~90 regs ->
// __launch_bounds__(256,1) so ptxas keeps both buffers live = MLP 32).
// ---------------------------------------------------------------------------
__global__ __launch_bounds__(256, 1)
void k_pq(const float* __restrict__ node,
          const float* __restrict__ We1,
          const float* __restrict__ be1) {
    __shared__ __align__(16) float xs[8][HH];
    int row0 = blockIdx.x * 8;
    int tid = threadIdx.x;
    int k = tid & 127;
    int half = tid >> 7;

#pragma unroll
    for (int q = 0; q < 4; q++) {
        int idx = tid + q * 256;
        xs[idx >> 7][idx & 127] = node[(row0 + (idx >> 7)) * HH + (idx & 127)];
    }
    __syncthreads();

    const float* W = We1 + half * HH * HH + k;
    float acc[8];
    float b = half ? 0.0f : be1[k];
#pragma unroll
    for (int r = 0; r < 8; r++) acc[r] = b;

    float w0[32], w1[32];
#pragma unroll
    for (int e = 0; e < 32; e++) w0[e] = W[e * HH];

#pragma unroll
    for (int c = 0; c < 4; c++) {
        float* wc = (c & 1) ? w1 : w0;
        float* wn = (c & 1) ? w0 : w1;
        if (c < 3) {
#pragma unroll
            for (int e = 0; e < 32; e++) wn[e] = W[((c + 1) * 32 + e) * HH];
        }
#pragma unroll
        for (int g = 0; g < 8; g++) {
#pragma unroll
            for (int r = 0; r < 8; r++) {
                float4 x = *(const float4*)&xs[r][c * 32 + g * 4];
                acc[r] = fmaf(x.x, wc[g * 4 + 0], acc[r]);
                acc[r] = fmaf(x.y, wc[g * 4 + 1], acc[r]);
                acc[r] = fmaf(x.z, wc[g * 4 + 2], acc[r]);
                acc[r] = fmaf(x.w, wc[g * 4 + 3], acc[r]);
            }
        }
    }
    float* dst = half ? g_Q : g_P;
#pragma unroll
    for (int r = 0; r < 8; r++)
        dst[(row0 + r) * HH + k] = 0.5f * acc[r];
}

// ---------------------------------------------------------------------------
// Kernel 2: S[b,i,k] += mj * silu(h),  h/2 = P'_i + Q'_j + dist*wd'
// silu(h) = (h/2)*(1 + tanh(h/2)).  grid (8, N/TI, B) = 1024 CTAs, 256 thr.
// Inner j-range == TJ: single tile load, single sync.
// ---------------------------------------------------------------------------
__global__ __launch_bounds__(256)
void k_edge(const float* __restrict__ pos,
            const float* __restrict__ mask,
            const float* __restrict__ We1) {
    __shared__ __align__(16) float qsm[TJ][HH];
    __shared__ __align__(16) float bsm[TI][HH];
    __shared__ float4 pjs[TJ];
    __shared__ float4 pis[TI];
    __shared__ float msm[TJ];

    int js = blockIdx.x;
    int i0 = blockIdx.y * TI;
    int b  = blockIdx.z;
    int tid = threadIdx.x;
    int j0 = js * TJ;

    for (int idx = tid; idx < TI * HH; idx += 256)
        bsm[idx >> 7][idx & 127] = g_P[(b * NN + i0 + (idx >> 7)) * HH + (idx & 127)];
    {
        const float4* qsrc = (const float4*)&g_Q[(b * NN + j0) * HH];
#pragma unroll
        for (int q = 0; q < 4; q++)
            ((float4*)qsm)[tid + q * 256] = qsrc[tid + q * 256];
    }
    if (tid < TI) {
        const float* p = &pos[(b * NN + i0 + tid) * 3];
        pis[tid] = make_float4(p[0], p[1], p[2], 0.0f);
    }
    if (tid >= 32 && tid < 32 + TJ) {
        int t = tid - 32;
        int jg = b * NN + j0 + t;
        const float* p = &pos[jg * 3];
        pjs[t] = make_float4(p[0], p[1], p[2], 0.0f);
        msm[t] = mask[jg];
    }
    __syncthreads();

    int il = tid >> 4;
    int k0 = (tid & 15) * 8;

    ull base2[4], wd2[4], acc2[4];
#pragma unroll
    for (int p = 0; p < 4; p++) {
        float wlo = 0.5f * We1[2 * HH * HH + k0 + 2 * p];
        float whi = 0.5f * We1[2 * HH * HH + k0 + 2 * p + 1];
        wd2[p] = pack2(wlo, whi);
        base2[p] = ((const ull*)&bsm[il][k0])[p];
        acc2[p] = 0ULL;
    }
    float4 pi = pis[il];

#pragma unroll 4
    for (int jl = 0; jl < TJ; jl++) {
        float4 pj = pjs[jl];
        float dx = pi.x - pj.x, dy = pi.y - pj.y, dz = pi.z - pj.z;
        float sq = fmaf(dx, dx, fmaf(dy, dy, dz * dz));
        float dist = (sq > 0.0f) ? sqrtfast(sq) : 0.0f;
        float mj = msm[jl];
        ull dist2 = pack2(dist, dist);
        ull mj2 = pack2(mj, mj);
        ulonglong2 qa = *(const ulonglong2*)&qsm[jl][k0];
        ulonglong2 qb = *(const ulonglong2*)&qsm[jl][k0 + 4];
        ull qv[4] = {qa.x, qa.y, qb.x, qb.y};
#pragma unroll
        for (int p = 0; p < 4; p++) {
            ull h2 = fma2(dist2, wd2[p], add2(base2[p], qv[p]));  // h/2
            float hl, hh; unpack2(h2, hl, hh);
            ull t2 = pack2(tanhfast(hl), tanhfast(hh));
            ull s2 = fma2(h2, t2, h2);        // silu(h) = h2*(1+t)
            acc2[p] = fma2(mj2, s2, acc2[p]); // += mj * silu
        }
    }
    float* dst = &g_S[js][(b * NN + i0 + il) * HH + k0];
#pragma unroll
    for (int p = 0; p < 4; p++) {
        float lo, hi; unpack2(acc2[p], lo, hi);
        dst[2 * p] = lo;
        dst[2 * p + 1] = hi;
    }
}

// ---------------------------------------------------------------------------
// Kernel 3: agg -> node MLP -> residual.  8 rows/CTA, 256 threads
// (thread = col k, row-half rb). Register double-buffered weights,
// __launch_bounds__(256,1) so the buffers stay resident.
// ---------------------------------------------------------------------------
__global__ __launch_bounds__(256, 1)
void k_final(const float* __restrict__ node,
             const float* __restrict__ mask,
             const float* __restrict__ We2,
             const float* __restrict__ be2,
             const float* __restrict__ Wn1,
             const float* __restrict__ bn1,
             const float* __restrict__ Wn2,
             const float* __restrict__ bn2,
             float* __restrict__ out) {
    __shared__ __align__(16) float Ssm[8][HH];
    __shared__ __align__(16) float XA[8][2 * HH];   // [X | A]
    __shared__ __align__(16) float Usm[8][HH];
    __shared__ float msk[8];
    __shared__ float cntsh;

    int row0 = blockIdx.x * 8;
    int b = row0 >> 8;
    int tid = threadIdx.x;
    int k = tid & 127;
    int rb = (tid >> 7) * 4;

#pragma unroll
    for (int q = 0; q < 4; q++) {
        int r = rb + q;
        int g = (row0 + r) * HH + k;
        XA[r][k] = node[g];
        float s = 0.0f;
#pragma unroll
        for (int t = 0; t < NSPLIT; t++) s += g_S[t][g];
        Ssm[r][k] = s;
    }
    if (tid < 8) msk[tid] = mask[row0 + tid];
    if (tid < 32) {
        float c = 0.0f;
#pragma unroll
        for (int m = 0; m < 8; m++) c += mask[b * NN + tid * 8 + m];
#pragma unroll
        for (int o = 16; o; o >>= 1) c += __shfl_xor_sync(0xffffffffu, c, o);
        if (tid == 0) cntsh = c;
    }
    __syncthreads();
    float cnt = cntsh;

    // Stage A: agg = msk*(S@We2 + cnt*be2)/max(msk*cnt,1)  -> XA[:, HH+k]
    {
        float acc[4] = {0.f, 0.f, 0.f, 0.f};
        const float* W = We2 + k;
        float w0[32], w1[32];
#pragma unroll
        for (int e = 0; e < 32; e++) w0[e] = W[e * HH];
#pragma unroll
        for (int c = 0; c < 4; c++) {
            float* wc = (c & 1) ? w1 : w0;
            float* wn = (c & 1) ? w0 : w1;
            if (c < 3) {
#pragma unroll
                for (int e = 0; e < 32; e++) wn[e] = W[((c + 1) * 32 + e) * HH];
            }
#pragma unroll
            for (int g = 0; g < 8; g++) {
#pragma unroll
                for (int q = 0; q < 4; q++) {
                    float4 s = *(const float4*)&Ssm[rb + q][c * 32 + g * 4];
                    acc[q] = fmaf(s.x, wc[g * 4 + 0], acc[q]);
                    acc[q] = fmaf(s.y, wc[g * 4 + 1], acc[q]);
                    acc[q] = fmaf(s.z, wc[g * 4 + 2], acc[q]);
                    acc[q] = fmaf(s.w, wc[g * 4 + 3], acc[q]);
                }
            }
        }
        float be2k = be2[k];
#pragma unroll
        for (int q = 0; q < 4; q++) {
            int r = rb + q;
            float denom = fmaxf(msk[r] * cnt, 1.0f);
            XA[r][HH + k] = msk[r] * (acc[q] + cnt * be2k) * (1.0f / denom);
        }
    }
    __syncthreads();

    // Stage B: u1 = silu(XA @ Wn1 + bn1)  (single 256-deep stream)
    {
        float b1 = bn1[k];
        float acc[4] = {b1, b1, b1, b1};
        const float* W = Wn1 + k;
        float w0[32], w1[32];
#pragma unroll
        for (int e = 0; e < 32; e++) w0[e] = W[e * HH];
#pragma unroll
        for (int c = 0; c < 8; c++) {
            float* wc = (c & 1) ? w1 : w0;
            float* wn = (c & 1) ? w0 : w1;
            if (c < 7) {
#pragma unroll
                for (int e = 0; e < 32; e++) wn[e] = W[((c + 1) * 32 + e) * HH];
            }
#pragma unroll
            for (int g = 0; g < 8; g++) {
#pragma unroll
                for (int q = 0; q < 4; q++) {
                    float4 x = *(const float4*)&XA[rb + q][c * 32 + g * 4];
                    acc[q] = fmaf(x.x, wc[g * 4 + 0], acc[q]);
                    acc[q] = fmaf(x.y, wc[g * 4 + 1], acc[q]);
                    acc[q] = fmaf(x.z, wc[g * 4 + 2], acc[q]);
                    acc[q] = fmaf(x.w, wc[g * 4 + 3], acc[q]);
                }
            }
        }
#pragma unroll
        for (int q = 0; q < 4; q++) {
            float h = acc[q];
            Usm[rb + q][k] = h * fast_sigmoid(h);
        }
    }
    __syncthreads();

    // Stage C: out = node + msk * (u1 @ Wn2 + bn2)
    {
        float b2 = bn2[k];
        float acc[4] = {b2, b2, b2, b2};
        const float* W = Wn2 + k;
        float w0[32], w1[32];
#pragma unroll
        for (int e = 0; e < 32; e++) w0[e] = W[e * HH];
#pragma unroll
        for (int c = 0; c < 4; c++) {
            float* wc = (c & 1) ? w1 : w0;
            float* wn = (c & 1) ? w0 : w1;
            if (c < 3) {
#pragma unroll
                for (int e = 0; e < 32; e++) wn[e] = W[((c + 1) * 32 + e) * HH];
            }
#pragma unroll
            for (int g = 0; g < 8; g++) {
#pragma unroll
                for (int q = 0; q < 4; q++) {
                    float4 u = *(const float4*)&Usm[rb + q][c * 32 + g * 4];
                    acc[q] = fmaf(u.x, wc[g * 4 + 0], acc[q]);
                    acc[q] = fmaf(u.y, wc[g * 4 + 1], acc[q]);
                    acc[q] = fmaf(u.z, wc[g * 4 + 2], acc[q]);
                    acc[q] = fmaf(u.w, wc[g * 4 + 3], acc[q]);
                }
            }
        }
#pragma unroll
        for (int q = 0; q < 4; q++) {
            int r = rb + q;
            out[(row0 + r) * HH + k] = XA[r][k] + msk[r] * acc[q];
        }
    }
}

extern "C" void kernel_launch(void* const* d_in, const int* in_sizes, int n_in,
                              void* d_out, int out_size) {
    (void)in_sizes; (void)n_in; (void)out_size;
    const float* node = (const float*)d_in[0];
    const float* pos  = (const float*)d_in[1];
    const float* mask = (const float*)d_in[2];
    const float* We1  = (const float*)d_in[3];
    const float* be1  = (const float*)d_in[4];
    const float* We2  = (const float*)d_in[5];
    const float* be2  = (const float*)d_in[6];
    const float* Wn1  = (const float*)d_in[7];
    const float* bn1  = (const float*)d_in[8];
    const float* Wn2  = (const float*)d_in[9];
    const float* bn2  = (const float*)d_in[10];
    float* out = (float*)d_out;

    k_pq<<<ROWS / 8, 256>>>(node, We1, be1);
    k_edge<<<dim3(NSPLIT, NN / TI, BB), 256>>>(pos, mask, We1);
    k_final<<<ROWS / 8, 256>>>(node, mask, We2, be2, Wn1, bn1, Wn2, bn2, out);
}

// round 5
// speedup vs baseline: 2.0090x; 1.0834x over previous
#include <cuda_runtime.h>
#include <cuda_bf16.h>

// Problem constants (B=8, N=256, H=128)
#define BB 8
#define NN 256
#define HH 128
#define ROWS (BB * NN)        // 2048
#define TI 16                 // i-rows per edge CTA
#define TJ 32                 // j-tile per edge CTA
#define NSPLIT 8              // j-range split (inner range == TJ)

typedef unsigned long long ull;

// Scratch (allocation-free rule: __device__ globals)
// g_P = 0.5*(node@We1a + be1); g_Q = 0.5*(node@We1b)  (pre-halved for tanh-silu)
__device__ float g_P[ROWS * HH];
__device__ float g_Q[ROWS * HH];
__device__ float g_S[NSPLIT][ROWS * HH];

// ---------------- packed f32x2 + MUFU helpers ----------------
__device__ __forceinline__ ull fma2(ull a, ull b, ull c) {
    ull d; asm("fma.rn.f32x2 %0, %1, %2, %3;" : "=l"(d) : "l"(a), "l"(b), "l"(c)); return d;
}
__device__ __forceinline__ ull add2(ull a, ull b) {
    ull d; asm("add.rn.f32x2 %0, %1, %2;" : "=l"(d) : "l"(a), "l"(b)); return d;
}
__device__ __forceinline__ ull pack2(float lo, float hi) {
    ull d; asm("mov.b64 %0, {%1, %2};" : "=l"(d) : "f"(lo), "f"(hi)); return d;
}
__device__ __forceinline__ void unpack2(ull v, float& lo, float& hi) {
    asm("mov.b64 {%0, %1}, %2;" : "=f"(lo), "=f"(hi) : "l"(v));
}
__device__ __forceinline__ float tanhfast(float x) {
    float y; asm("tanh.approx.f32 %0, %1;" : "=f"(y) : "f"(x)); return y;
}
__device__ __forceinline__ float sqrtfast(float x) {
    float y; asm("sqrt.approx.f32 %0, %1;" : "=f"(y) : "f"(x)); return y;
}
__device__ __forceinline__ float fast_sigmoid(float x) {
    float e; asm("ex2.approx.f32 %0, %1;" : "=f"(e) : "f"(-1.4426950408889634f * x));
    float r; asm("rcp.approx.f32 %0, %1;" : "=f"(r) : "f"(1.0f + e));
    return r;
}

// ---------------------------------------------------------------------------
// Kernel 1: P' = 0.5*(node@We1a + be1) ; Q' = 0.5*(node@We1b)
// 16 rows/CTA, 512 threads -> grid 128 = single wave.
// tid bits: [0:7)=k, bit7=half (P/Q), bit8=row-group (8 rows each).
// ---------------------------------------------------------------------------
__global__ __launch_bounds__(512, 1)
void k_pq(const float* __restrict__ node,
          const float* __restrict__ We1,
          const float* __restrict__ be1) {
    __shared__ __align__(16) float xs[16][HH];
    int row0 = blockIdx.x * 16;
    int tid = threadIdx.x;
    int k = tid & 127;
    int half = (tid >> 7) & 1;
    int r0 = (tid >> 8) * 8;

#pragma unroll
    for (int q = 0; q < 4; q++) {
        int idx = tid + q * 512;
        xs[idx >> 7][idx & 127] = node[(row0 + (idx >> 7)) * HH + (idx & 127)];
    }
    __syncthreads();

    const float* W = We1 + half * HH * HH + k;
    float acc[8];
    float b = half ? 0.0f : be1[k];
#pragma unroll
    for (int r = 0; r < 8; r++) acc[r] = b;

    float w0[16], w1[16];
#pragma unroll
    for (int e = 0; e < 16; e++) w0[e] = W[e * HH];

#pragma unroll
    for (int c = 0; c < 8; c++) {
        float* wc = (c & 1) ? w1 : w0;
        float* wn = (c & 1) ? w0 : w1;
        if (c < 7) {
#pragma unroll
            for (int e = 0; e < 16; e++) wn[e] = W[((c + 1) * 16 + e) * HH];
        }
#pragma unroll
        for (int g = 0; g < 4; g++) {
#pragma unroll
            for (int r = 0; r < 8; r++) {
                float4 x = *(const float4*)&xs[r0 + r][c * 16 + g * 4];
                acc[r] = fmaf(x.x, wc[g * 4 + 0], acc[r]);
                acc[r] = fmaf(x.y, wc[g * 4 + 1], acc[r]);
                acc[r] = fmaf(x.z, wc[g * 4 + 2], acc[r]);
                acc[r] = fmaf(x.w, wc[g * 4 + 3], acc[r]);
            }
        }
    }
    float* dst = half ? g_Q : g_P;
#pragma unroll
    for (int r = 0; r < 8; r++)
        dst[(row0 + r0 + r) * HH + k] = 0.5f * acc[r];
}

// ---------------------------------------------------------------------------
// Kernel 2: S[b,i,k] += mj * silu(h),  h/2 = P'_i + Q'_j + dist*wd'
// dist precomputed once per (il,jl) into smem (was 16x redundant).
// grid (8, N/TI, B) = 1024 CTAs, 256 threads, single prologue sync.
// ---------------------------------------------------------------------------
__global__ __launch_bounds__(256)
void k_edge(const float* __restrict__ pos,
            const float* __restrict__ mask,
            const float* __restrict__ We1) {
    __shared__ __align__(16) float qsm[TJ][HH];   // 16 KB
    __shared__ __align__(16) float bsm[TI][HH];   // 8 KB
    __shared__ float dsm[TI][TJ];                 // 2 KB
    __shared__ float msm[TJ];

    int js = blockIdx.x;
    int i0 = blockIdx.y * TI;
    int b  = blockIdx.z;
    int tid = threadIdx.x;
    int j0 = js * TJ;

#pragma unroll
    for (int q = 0; q < 8; q++) {
        int idx = tid + q * 256;
        bsm[idx >> 7][idx & 127] = g_P[(b * NN + i0 + (idx >> 7)) * HH + (idx & 127)];
    }
    {
        const float4* qsrc = (const float4*)&g_Q[(b * NN + j0) * HH];
#pragma unroll
        for (int q = 0; q < 4; q++)
            ((float4*)qsm)[tid + q * 256] = qsrc[tid + q * 256];
    }
    if (tid < TJ) msm[tid] = mask[b * NN + j0 + tid];
    // dist tile: 512 pairs / 256 threads = 2 each (pos reads are L2-hot)
#pragma unroll
    for (int t = 0; t < 2; t++) {
        int idx = tid + t * 256;
        int il = idx >> 5, jl = idx & 31;
        const float* pi = &pos[(b * NN + i0 + il) * 3];
        const float* pj = &pos[(b * NN + j0 + jl) * 3];
        float dx = pi[0] - pj[0], dy = pi[1] - pj[1], dz = pi[2] - pj[2];
        float sq = fmaf(dx, dx, fmaf(dy, dy, dz * dz));
        dsm[il][jl] = (sq > 0.0f) ? sqrtfast(sq) : 0.0f;
    }
    __syncthreads();

    int il = tid >> 4;
    int k0 = (tid & 15) * 8;

    ull base2[4], wd2[4], acc2[4];
#pragma unroll
    for (int p = 0; p < 4; p++) {
        float wlo = 0.5f * We1[2 * HH * HH + k0 + 2 * p];
        float whi = 0.5f * We1[2 * HH * HH + k0 + 2 * p + 1];
        wd2[p] = pack2(wlo, whi);
        base2[p] = ((const ull*)&bsm[il][k0])[p];
        acc2[p] = 0ULL;
    }

#pragma unroll 4
    for (int jl = 0; jl < TJ; jl++) {
        float dist = dsm[il][jl];
        float mj = msm[jl];
        ull dist2 = pack2(dist, dist);
        ull mj2 = pack2(mj, mj);
        ulonglong2 qa = *(const ulonglong2*)&qsm[jl][k0];
        ulonglong2 qb = *(const ulonglong2*)&qsm[jl][k0 + 4];
        ull qv[4] = {qa.x, qa.y, qb.x, qb.y};
#pragma unroll
        for (int p = 0; p < 4; p++) {
            ull h2 = fma2(dist2, wd2[p], add2(base2[p], qv[p]));  // h/2
            float hl, hh; unpack2(h2, hl, hh);
            ull t2 = pack2(tanhfast(hl), tanhfast(hh));
            ull s2 = fma2(h2, t2, h2);        // silu(h) = h2*(1+t)
            acc2[p] = fma2(mj2, s2, acc2[p]); // += mj * silu
        }
    }
    float* dst = &g_S[js][(b * NN + i0 + il) * HH + k0];
#pragma unroll
    for (int p = 0; p < 4; p++) {
        float lo, hi; unpack2(acc2[p], lo, hi);
        dst[2 * p] = lo;
        dst[2 * p + 1] = hi;
    }
}

// ---------------------------------------------------------------------------
// Kernel 3: agg -> node MLP -> residual.  16 rows/CTA, 512 threads,
// grid 128 = single wave. tid bits: [0:7)=k, [7:9)=row-quarter (4 rows each).
// ---------------------------------------------------------------------------
__global__ __launch_bounds__(512, 1)
void k_final(const float* __restrict__ node,
             const float* __restrict__ mask,
             const float* __restrict__ We2,
             const float* __restrict__ be2,
             const float* __restrict__ Wn1,
             const float* __restrict__ bn1,
             const float* __restrict__ Wn2,
             const float* __restrict__ bn2,
             float* __restrict__ out) {
    __shared__ __align__(16) float Ssm[16][HH];     // 8 KB
    __shared__ __align__(16) float XA[16][2 * HH];  // 16 KB  [X | A]
    __shared__ __align__(16) float Usm[16][HH];     // 8 KB
    __shared__ float msk[16];
    __shared__ float cntsh;

    int row0 = blockIdx.x * 16;
    int b = row0 >> 8;
    int tid = threadIdx.x;
    int k = tid & 127;
    int rb = (tid >> 7) * 4;

#pragma unroll
    for (int q = 0; q < 4; q++) {
        int r = rb + q;
        int g = (row0 + r) * HH + k;
        XA[r][k] = node[g];
        float s = 0.0f;
#pragma unroll
        for (int t = 0; t < NSPLIT; t++) s += g_S[t][g];
        Ssm[r][k] = s;
    }
    if (tid < 16) msk[tid] = mask[row0 + tid];
    if (tid < 32) {
        float c = 0.0f;
#pragma unroll
        for (int m = 0; m < 8; m++) c += mask[b * NN + tid * 8 + m];
#pragma unroll
        for (int o = 16; o; o >>= 1) c += __shfl_xor_sync(0xffffffffu, c, o);
        if (tid == 0) cntsh = c;
    }
    __syncthreads();
    float cnt = cntsh;

    // Stage A: agg = msk*(S@We2 + cnt*be2)/max(msk*cnt,1) -> XA[:, HH+k]
    {
        float acc[4] = {0.f, 0.f, 0.f, 0.f};
        const float* W = We2 + k;
        float w0[16], w1[16];
#pragma unroll
        for (int e = 0; e < 16; e++) w0[e] = W[e * HH];
#pragma unroll
        for (int c = 0; c < 8; c++) {
            float* wc = (c & 1) ? w1 : w0;
            float* wn = (c & 1) ? w0 : w1;
            if (c < 7) {
#pragma unroll
                for (int e = 0; e < 16; e++) wn[e] = W[((c + 1) * 16 + e) * HH];
            }
#pragma unroll
            for (int g = 0; g < 4; g++) {
#pragma unroll
                for (int q = 0; q < 4; q++) {
                    float4 s = *(const float4*)&Ssm[rb + q][c * 16 + g * 4];
                    acc[q] = fmaf(s.x, wc[g * 4 + 0], acc[q]);
                    acc[q] = fmaf(s.y, wc[g * 4 + 1], acc[q]);
                    acc[q] = fmaf(s.z, wc[g * 4 + 2], acc[q]);
                    acc[q] = fmaf(s.w, wc[g * 4 + 3], acc[q]);
                }
            }
        }
        float be2k = be2[k];
#pragma unroll
        for (int q = 0; q < 4; q++) {
            int r = rb + q;
            float denom = fmaxf(msk[r] * cnt, 1.0f);
            XA[r][HH + k] = msk[r] * (acc[q] + cnt * be2k) * (1.0f / denom);
        }
    }
    __syncthreads();

    // Stage B: u1 = silu(XA @ Wn1 + bn1)
    {
        float b1 = bn1[k];
        float acc[4] = {b1, b1, b1, b1};
        const float* W = Wn1 + k;
        float w0[16], w1[16];
#pragma unroll
        for (int e = 0; e < 16; e++) w0[e] = W[e * HH];
#pragma unroll
        for (int c = 0; c < 16; c++) {
            float* wc = (c & 1) ? w1 : w0;
            float* wn = (c & 1) ? w0 : w1;
            if (c < 15) {
#pragma unroll
                for (int e = 0; e < 16; e++) wn[e] = W[((c + 1) * 16 + e) * HH];
            }
#pragma unroll
            for (int g = 0; g < 4; g++) {
#pragma unroll
                for (int q = 0; q < 4; q++) {
                    float4 x = *(const float4*)&XA[rb + q][c * 16 + g * 4];
                    acc[q] = fmaf(x.x, wc[g * 4 + 0], acc[q]);
                    acc[q] = fmaf(x.y, wc[g * 4 + 1], acc[q]);
                    acc[q] = fmaf(x.z, wc[g * 4 + 2], acc[q]);
                    acc[q] = fmaf(x.w, wc[g * 4 + 3], acc[q]);
                }
            }
        }
#pragma unroll
        for (int q = 0; q < 4; q++) {
            float h = acc[q];
            Usm[rb + q][k] = h * fast_sigmoid(h);
        }
    }
    __syncthreads();

    // Stage C: out = node + msk * (u1 @ Wn2 + bn2)
    {
        float b2 = bn2[k];
        float acc[4] = {b2, b2, b2, b2};
        const float* W = Wn2 + k;
        float w0[16], w1[16];
#pragma unroll
        for (int e = 0; e < 16; e++) w0[e] = W[e * HH];
#pragma unroll
        for (int c = 0; c < 8; c++) {
            float* wc = (c & 1) ? w1 : w0;
            float* wn = (c & 1) ? w0 : w1;
            if (c < 7) {
#pragma unroll
                for (int e = 0; e < 16; e++) wn[e] = W[((c + 1) * 16 + e) * HH];
            }
#pragma unroll
            for (int g = 0; g < 4; g++) {
#pragma unroll
                for (int q = 0; q < 4; q++) {
                    float4 u = *(const float4*)&Usm[rb + q][c * 16 + g * 4];
                    acc[q] = fmaf(u.x, wc[g * 4 + 0], acc[q]);
                    acc[q] = fmaf(u.y, wc[g * 4 + 1], acc[q]);
                    acc[q] = fmaf(u.z, wc[g * 4 + 2], acc[q]);
                    acc[q] = fmaf(u.w, wc[g * 4 + 3], acc[q]);
                }
            }
        }
#pragma unroll
        for (int q = 0; q < 4; q++) {
            int r = rb + q;
            out[(row0 + r) * HH + k] = XA[r][k] + msk[r] * acc[q];
        }
    }
}

extern "C" void kernel_launch(void* const* d_in, const int* in_sizes, int n_in,
                              void* d_out, int out_size) {
    (void)in_sizes; (void)n_in; (void)out_size;
    const float* node = (const float*)d_in[0];
    const float* pos  = (const float*)d_in[1];
    const float* mask = (const float*)d_in[2];
    const float* We1  = (const float*)d_in[3];
    const float* be1  = (const float*)d_in[4];
    const float* We2  = (const float*)d_in[5];
    const float* be2  = (const float*)d_in[6];
    const float* Wn1  = (const float*)d_in[7];
    const float* bn1  = (const float*)d_in[8];
    const float* Wn2  = (const float*)d_in[9];
    const float* bn2  = (const float*)d_in[10];
    float* out = (float*)d_out;

    k_pq<<<ROWS / 16, 512>>>(node, We1, be1);
    k_edge<<<dim3(NSPLIT, NN / TI, BB), 256>>>(pos, mask, We1);
    k_final<<<ROWS / 16, 512>>>(node, mask, We2, be2, Wn1, bn1, Wn2, bn2, out);
}